// round 2
// baseline (speedup 1.0000x reference)
#include <cuda_runtime.h>
#include <cstdint>

#define H   128
#define ED  32
#define NH  4
#define DH  32
#define TD  32
#define MH  256

#define MAXN 50048
#define MAXE 640064

// ---------------- scratch (module-level device memory; no allocs) ----------
__device__ __align__(128) float    g_hq  [(size_t)MAXN * H];
__device__ __align__(128) float    g_hk  [(size_t)MAXN * H];
__device__ __align__(128) float    g_hm1 [(size_t)MAXN * H];   // h @ W1a + b1
__device__ __align__(128) float    g_scores[(size_t)MAXE * NH];
__device__ __align__(128) float    g_ex    [(size_t)MAXE * NH];
__device__ __align__(128) unsigned g_smax  [(size_t)MAXN * NH];
__device__ __align__(128) float    g_den   [(size_t)MAXN * NH];
__device__ __align__(128) float    g_agg   [(size_t)MAXN * H];

// ---------------- helpers ---------------------------------------------------
__device__ __forceinline__ unsigned enc_f(float f) {
    unsigned u = __float_as_uint(f);
    return (u & 0x80000000u) ? ~u : (u | 0x80000000u);
}
__device__ __forceinline__ float dec_f(unsigned k) {
    unsigned u = (k & 0x80000000u) ? (k & 0x7FFFFFFFu) : ~k;
    return __uint_as_float(u);
}
__device__ __forceinline__ float silu_f(float x) {
    return x / (1.0f + __expf(-x));
}
__device__ __forceinline__ void red_add_v4(float* p, float4 v) {
    asm volatile("red.global.add.v4.f32 [%0], {%1,%2,%3,%4};"
                 :: "l"(p), "f"(v.x), "f"(v.y), "f"(v.z), "f"(v.w) : "memory");
}
__device__ __forceinline__ void fma4(float4& acc, float a, const float4& b) {
    acc.x = fmaf(a, b.x, acc.x);
    acc.y = fmaf(a, b.y, acc.y);
    acc.z = fmaf(a, b.z, acc.z);
    acc.w = fmaf(a, b.w, acc.w);
}

// ============================================================================
// K1: node projections  hq = h@wq, hk = h@wk, hm1 = h@W1a + b1
// 32 rows/block, 256 threads, weights streamed through smem in 32-k slabs.
// ============================================================================
__global__ void __launch_bounds__(256) k1_proj(
    const float* __restrict__ h,
    const float* __restrict__ wq, const float* __restrict__ wk,
    const float* __restrict__ mw1, const float* __restrict__ mb1, int N)
{
    __shared__ float sa[32 * H];
    __shared__ float sw[32 * H];
    const int tid  = threadIdx.x;
    const int row0 = blockIdx.x * 32;

    for (int i = tid; i < 32 * H / 4; i += 256) {
        int r = i >> 5, c4 = i & 31;
        float4 v = make_float4(0.f, 0.f, 0.f, 0.f);
        if (row0 + r < N) v = ((const float4*)(h + (size_t)(row0 + r) * H))[c4];
        ((float4*)sa)[i] = v;
    }
    __syncthreads();

    const int cg = tid & 31, rg = tid >> 5, c0 = cg << 2;

    #pragma unroll
    for (int m = 0; m < 3; m++) {
        const float* W = (m == 0) ? wq : (m == 1) ? wk : mw1;
        float4 acc[4];
        if (m == 2) {
            float4 b = ((const float4*)mb1)[cg];
            acc[0] = acc[1] = acc[2] = acc[3] = b;
        } else {
            acc[0] = acc[1] = acc[2] = acc[3] = make_float4(0.f, 0.f, 0.f, 0.f);
        }
        for (int ks = 0; ks < 4; ks++) {
            __syncthreads();
            for (int i = tid; i < 32 * H / 4; i += 256)
                ((float4*)sw)[i] = ((const float4*)(W + (size_t)ks * 32 * H))[i];
            __syncthreads();
            #pragma unroll
            for (int kk = 0; kk < 32; kk++) {
                float4 w4 = *(const float4*)&sw[kk * H + c0];
                #pragma unroll
                for (int i = 0; i < 4; i++) {
                    float a = sa[(rg * 4 + i) * H + ks * 32 + kk];
                    fma4(acc[i], a, w4);
                }
            }
        }
        float* O = (m == 0) ? g_hq : (m == 1) ? g_hk : g_hm1;
        #pragma unroll
        for (int i = 0; i < 4; i++) {
            int r = rg * 4 + i;
            if (row0 + r < N)
                *(float4*)&O[(size_t)(row0 + r) * H + c0] = acc[i];
        }
    }
}

// ============================================================================
// K2: per-edge attention scores + segment max.
// warp per edge: k_e = hk[src] + dt_feat@wt ; score = q.k / sqrt(DH)
// ============================================================================
__global__ void __launch_bounds__(256) k2_scores(
    const float* __restrict__ wt,
    const float* __restrict__ tfreq, const float* __restrict__ tphase,
    const int* __restrict__ eidx, const float* __restrict__ dts, int E)
{
    __shared__ float swt[TD * H];
    __shared__ float sfreq[TD], sphase[TD];
    __shared__ float sdtf[8][TD];
    const int tid = threadIdx.x;
    for (int i = tid; i < TD * H / 4; i += 256)
        ((float4*)swt)[i] = ((const float4*)wt)[i];
    if (tid < TD) { sfreq[tid] = tfreq[tid]; sphase[tid] = tphase[tid]; }
    __syncthreads();

    const int warp = tid >> 5, lane = tid & 31;
    const int c0 = lane << 2;
    for (int e = blockIdx.x * 8 + warp; e < E; e += gridDim.x * 8) {
        int tgt = eidx[e];
        int src = eidx[E + e];
        float dt = dts[e];
        sdtf[warp][lane] = cosf(dt * sfreq[lane] + sphase[lane]);
        __syncwarp();

        float4 kv = *(const float4*)&g_hk[(size_t)src * H + c0];
        #pragma unroll
        for (int d = 0; d < TD; d++) {
            float f = sdtf[warp][d];
            float4 w4 = *(const float4*)&swt[d * H + c0];
            fma4(kv, f, w4);
        }
        float4 q4 = *(const float4*)&g_hq[(size_t)tgt * H + c0];
        float p = q4.x * kv.x + q4.y * kv.y + q4.z * kv.z + q4.w * kv.w;
        p += __shfl_xor_sync(0xffffffffu, p, 4);
        p += __shfl_xor_sync(0xffffffffu, p, 2);
        p += __shfl_xor_sync(0xffffffffu, p, 1);
        if ((lane & 7) == 0) {
            float s = p * 0.17677669529663687f;   // 1/sqrt(32)
            int hd = lane >> 3;
            g_scores[(size_t)e * NH + hd] = s;
            atomicMax(&g_smax[(size_t)tgt * NH + hd], enc_f(s));
        }
        __syncwarp();
    }
}

// ============================================================================
// K3: ex = exp(score - smax[tgt]); den[tgt] += ex   (one thread per edge)
// ============================================================================
__global__ void __launch_bounds__(256) k3_softmax(
    const int* __restrict__ eidx, int E)
{
    int e = blockIdx.x * 256 + threadIdx.x;
    if (e >= E) return;
    int tgt = eidx[e];
    float4 s4 = *(const float4*)&g_scores[(size_t)e * NH];
    uint4  m4 = *(const uint4*)&g_smax[(size_t)tgt * NH];
    float4 v;
    v.x = __expf(s4.x - dec_f(m4.x));
    v.y = __expf(s4.y - dec_f(m4.y));
    v.z = __expf(s4.z - dec_f(m4.z));
    v.w = __expf(s4.w - dec_f(m4.w));
    *(float4*)&g_ex[(size_t)e * NH] = v;
    red_add_v4(&g_den[(size_t)tgt * NH], v);
}

// ============================================================================
// K4: edge message MLP + attention-weighted scatter.
// hid = silu(hm1[src] + e@W1b)  (b1 folded into hm1)
// m   = hid @ msg_w2 + b2 ; agg[tgt] += attn * m   (red.global.add.v4)
// Persistent blocks; W1b + msg_w2 resident in shared.  32-edge tiles.
// ============================================================================
#define SMEM4_FLOATS (4096 + 16384 + 1024 + 4096 + 128 + 32)
#define SMEM4_BYTES  (SMEM4_FLOATS * 4)

__global__ void __launch_bounds__(256) k4_edge(
    const float* __restrict__ ef, const float* __restrict__ w1b,
    const float* __restrict__ w2, const float* __restrict__ b2,
    const int* __restrict__ eidx, int E)
{
    extern __shared__ float sm4[];
    float* sw1b = sm4;                 // [32][128]
    float* sw2  = sm4 + 4096;          // [128][128]
    float* sef  = sm4 + 20480;         // [32][32]
    float* shid = sm4 + 21504;         // [32][128]
    float* satt = sm4 + 25600;         // [32][4]
    int*   stgt = (int*)(sm4 + 25728); // [32]

    const int tid = threadIdx.x;
    for (int i = tid; i < 4096 / 4; i += 256)
        ((float4*)sw1b)[i] = ((const float4*)w1b)[i];
    for (int i = tid; i < 16384 / 4; i += 256)
        ((float4*)sw2)[i] = ((const float4*)w2)[i];

    const int cg = tid & 31, rg = tid >> 5, c0 = cg << 2, hd = cg >> 3;
    const float4 b2v = ((const float4*)b2)[cg];
    const int ntiles = (E + 31) >> 5;

    for (int tile = blockIdx.x; tile < ntiles; tile += gridDim.x) {
        const int e0 = tile << 5;
        __syncthreads();   // protects smem from previous tile (and weight loads, tile 0)

        if (tid < 128) {
            int r = tid >> 2, hh = tid & 3;
            int e = e0 + r;
            float a = 0.f; int tg = 0;
            if (e < E) {
                tg = eidx[e];
                a  = g_ex[(size_t)e * NH + hh] / g_den[(size_t)tg * NH + hh];
            }
            satt[r * 4 + hh] = a;
            if (hh == 0) stgt[r] = tg;
        }
        for (int i = tid; i < 1024 / 4; i += 256) {
            int r = i >> 3, c4 = i & 7;
            int e = e0 + r;
            float4 v = make_float4(0.f, 0.f, 0.f, 0.f);
            if (e < E) v = ((const float4*)(ef + (size_t)e * ED))[c4];
            ((float4*)sef)[i] = v;
        }
        __syncthreads();

        // phase A: pre-activation = hm1[src] + ef @ W1b, then silu -> shid
        float4 acc[4];
        #pragma unroll
        for (int i = 0; i < 4; i++) {
            int e = e0 + rg * 4 + i;
            int src = (e < E) ? eidx[E + e] : 0;
            acc[i] = *(const float4*)&g_hm1[(size_t)src * H + c0];
        }
        #pragma unroll
        for (int d = 0; d < ED; d++) {
            float4 w4 = *(const float4*)&sw1b[d * H + c0];
            #pragma unroll
            for (int i = 0; i < 4; i++) {
                float f = sef[(rg * 4 + i) * ED + d];
                fma4(acc[i], f, w4);
            }
        }
        #pragma unroll
        for (int i = 0; i < 4; i++) {
            float4 s;
            s.x = silu_f(acc[i].x); s.y = silu_f(acc[i].y);
            s.z = silu_f(acc[i].z); s.w = silu_f(acc[i].w);
            *(float4*)&shid[(rg * 4 + i) * H + c0] = s;
        }
        __syncthreads();

        // phase B: m = hid @ msg_w2 + b2
        float4 m4[4];
        #pragma unroll
        for (int i = 0; i < 4; i++) m4[i] = b2v;
        #pragma unroll 8
        for (int k = 0; k < H; k++) {
            float4 w4 = *(const float4*)&sw2[k * H + c0];
            #pragma unroll
            for (int i = 0; i < 4; i++) {
                float a = shid[(rg * 4 + i) * H + k];
                fma4(m4[i], a, w4);
            }
        }
        // phase C: scatter attn * m
        #pragma unroll
        for (int i = 0; i < 4; i++) {
            int r = rg * 4 + i, e = e0 + r;
            if (e < E) {
                float a  = satt[r * 4 + hd];
                int   tg = stgt[r];
                float4 v = make_float4(a * m4[i].x, a * m4[i].y,
                                       a * m4[i].z, a * m4[i].w);
                red_add_v4(&g_agg[(size_t)tg * H + c0], v);
            }
        }
    }
}

// ============================================================================
// K5: per-node output:  aggregated = agg@wo ; x=[h||aggregated||t_feat] ;
//     dh = (silu(silu(x@w1+b1)@w2+b2))@w3 + b3
// 32 nodes/block, weight slabs streamed through shared (L2-resident).
// ============================================================================
#define SMEM5_FLOATS (9216 + 8192 + 8192)
#define SMEM5_BYTES  (SMEM5_FLOATS * 4)

__global__ void __launch_bounds__(256) k5_out(
    const float* __restrict__ h,  const float* __restrict__ wo,
    const float* __restrict__ w1, const float* __restrict__ b1,
    const float* __restrict__ w2, const float* __restrict__ b2,
    const float* __restrict__ w3, const float* __restrict__ b3,
    const float* __restrict__ tptr,
    const float* __restrict__ tfreq, const float* __restrict__ tphase,
    float* __restrict__ out, int N)
{
    extern __shared__ float sm5[];
    float* sx = sm5;                 // [32][288]
    float* sy = sm5 + 9216;          // [32][256]
    float* sw = sm5 + 9216 + 8192;   // up to [32][256]

    const int tid  = threadIdx.x;
    const int row0 = blockIdx.x * 32;
    const float t  = tptr[0];

    // t_feat (same vector for all rows)
    for (int i = tid; i < 32 * TD; i += 256) {
        int r = i >> 5, j = i & 31;
        sx[r * 288 + 256 + j] = cosf(t * tfreq[j] + tphase[j]);
    }
    // h block -> sx[:, 0:128]
    for (int i = tid; i < 32 * H / 4; i += 256) {
        int r = i >> 5, c4 = i & 31;
        float4 v = make_float4(0.f, 0.f, 0.f, 0.f);
        if (row0 + r < N) v = ((const float4*)(h + (size_t)(row0 + r) * H))[c4];
        *(float4*)&sx[r * 288 + c4 * 4] = v;
    }
    // agg block -> sy (temporary A-tile)
    for (int i = tid; i < 32 * H / 4; i += 256) {
        int r = i >> 5, c4 = i & 31;
        float4 v = make_float4(0.f, 0.f, 0.f, 0.f);
        if (row0 + r < N) v = ((const float4*)(g_agg + (size_t)(row0 + r) * H))[c4];
        ((float4*)sy)[i] = v;
    }
    __syncthreads();

    const int cg = tid & 31, rg = tid >> 5, c0 = cg << 2;

    // stage 0: aggregated = aggtile @ wo  -> sx[:, 128:256]
    {
        float4 acc[4];
        #pragma unroll
        for (int i = 0; i < 4; i++) acc[i] = make_float4(0.f, 0.f, 0.f, 0.f);
        for (int ks = 0; ks < 4; ks++) {
            __syncthreads();
            for (int i = tid; i < 32 * H / 4; i += 256)
                ((float4*)sw)[i] = ((const float4*)(wo + (size_t)ks * 32 * H))[i];
            __syncthreads();
            #pragma unroll
            for (int kk = 0; kk < 32; kk++) {
                float4 w4 = *(const float4*)&sw[kk * H + c0];
                #pragma unroll
                for (int i = 0; i < 4; i++) {
                    float a = sy[(rg * 4 + i) * H + ks * 32 + kk];
                    fma4(acc[i], a, w4);
                }
            }
        }
        __syncthreads();
        #pragma unroll
        for (int i = 0; i < 4; i++)
            *(float4*)&sx[(rg * 4 + i) * 288 + 128 + c0] = acc[i];
    }
    __syncthreads();

    const int cgB = tid & 63, rgB = tid >> 6, cB0 = cgB << 2;

    // stage 1: y1 = silu(x @ w1 + b1) -> sy [32][256]
    {
        float4 acc[8];
        float4 bb = ((const float4*)b1)[cgB];
        #pragma unroll
        for (int i = 0; i < 8; i++) acc[i] = bb;
        for (int ks = 0; ks < 9; ks++) {
            __syncthreads();
            for (int i = tid; i < 32 * MH / 4; i += 256)
                ((float4*)sw)[i] = ((const float4*)(w1 + (size_t)ks * 32 * MH))[i];
            __syncthreads();
            #pragma unroll
            for (int kk = 0; kk < 32; kk++) {
                float4 w4 = *(const float4*)&sw[kk * MH + cB0];
                #pragma unroll
                for (int i = 0; i < 8; i++) {
                    float a = sx[(rgB * 8 + i) * 288 + ks * 32 + kk];
                    fma4(acc[i], a, w4);
                }
            }
        }
        __syncthreads();
        #pragma unroll
        for (int i = 0; i < 8; i++) {
            float4 s;
            s.x = silu_f(acc[i].x); s.y = silu_f(acc[i].y);
            s.z = silu_f(acc[i].z); s.w = silu_f(acc[i].w);
            *(float4*)&sy[(rgB * 8 + i) * MH + cB0] = s;
        }
    }
    __syncthreads();

    // stage 2: y2 = silu(y1 @ w2 + b2) -> sx rows (stride 288), cols 0:256
    {
        float4 acc[8];
        float4 bb = ((const float4*)b2)[cgB];
        #pragma unroll
        for (int i = 0; i < 8; i++) acc[i] = bb;
        for (int ks = 0; ks < 8; ks++) {
            __syncthreads();
            for (int i = tid; i < 32 * MH / 4; i += 256)
                ((float4*)sw)[i] = ((const float4*)(w2 + (size_t)ks * 32 * MH))[i];
            __syncthreads();
            #pragma unroll
            for (int kk = 0; kk < 32; kk++) {
                float4 w4 = *(const float4*)&sw[kk * MH + cB0];
                #pragma unroll
                for (int i = 0; i < 8; i++) {
                    float a = sy[(rgB * 8 + i) * MH + ks * 32 + kk];
                    fma4(acc[i], a, w4);
                }
            }
        }
        __syncthreads();
        #pragma unroll
        for (int i = 0; i < 8; i++) {
            float4 s;
            s.x = silu_f(acc[i].x); s.y = silu_f(acc[i].y);
            s.z = silu_f(acc[i].z); s.w = silu_f(acc[i].w);
            *(float4*)&sx[(rgB * 8 + i) * 288 + cB0] = s;
        }
    }
    __syncthreads();

    // stage 3: out = y2 @ w3 + b3
    {
        float4 acc[4];
        float4 bb = ((const float4*)b3)[cg];
        #pragma unroll
        for (int i = 0; i < 4; i++) acc[i] = bb;
        for (int ks = 0; ks < 8; ks++) {
            __syncthreads();
            for (int i = tid; i < 32 * H / 4; i += 256)
                ((float4*)sw)[i] = ((const float4*)(w3 + (size_t)ks * 32 * H))[i];
            __syncthreads();
            #pragma unroll
            for (int kk = 0; kk < 32; kk++) {
                float4 w4 = *(const float4*)&sw[kk * H + c0];
                #pragma unroll
                for (int i = 0; i < 4; i++) {
                    float a = sx[(rg * 4 + i) * 288 + ks * 32 + kk];
                    fma4(acc[i], a, w4);
                }
            }
        }
        #pragma unroll
        for (int i = 0; i < 4; i++) {
            int r = rg * 4 + i;
            if (row0 + r < N)
                *(float4*)&out[(size_t)(row0 + r) * H + c0] = acc[i];
        }
    }
}

// ============================================================================
extern "C" void kernel_launch(void* const* d_in, const int* in_sizes, int n_in,
                              void* d_out, int out_size)
{
    // num_nodes (python int) may or may not appear as input #5; detect by size.
    int wbase = (in_sizes[5] == (H + ED) * H) ? 5 : 6;

    const float* t_ptr  = (const float*)d_in[0];
    const float* h      = (const float*)d_in[1];
    const int*   eidx   = (const int*)  d_in[2];
    const float* ef     = (const float*)d_in[3];
    const float* dts    = (const float*)d_in[4];
    const float* msg_w1 = (const float*)d_in[wbase + 0];
    const float* msg_b1 = (const float*)d_in[wbase + 1];
    const float* msg_w2 = (const float*)d_in[wbase + 2];
    const float* msg_b2 = (const float*)d_in[wbase + 3];
    const float* wq     = (const float*)d_in[wbase + 4];
    const float* wk     = (const float*)d_in[wbase + 5];
    const float* wt     = (const float*)d_in[wbase + 6];
    const float* wo     = (const float*)d_in[wbase + 7];
    const float* tfreq  = (const float*)d_in[wbase + 8];
    const float* tphase = (const float*)d_in[wbase + 9];
    const float* nw1    = (const float*)d_in[wbase + 10];
    const float* nb1    = (const float*)d_in[wbase + 11];
    const float* nw2    = (const float*)d_in[wbase + 12];
    const float* nb2    = (const float*)d_in[wbase + 13];
    const float* nw3    = (const float*)d_in[wbase + 14];
    const float* nb3    = (const float*)d_in[wbase + 15];
    float* out = (float*)d_out;

    const int N = in_sizes[1] / H;
    const int E = in_sizes[4];

    void *p_smax, *p_den, *p_agg;
    cudaGetSymbolAddress(&p_smax, g_smax);
    cudaGetSymbolAddress(&p_den,  g_den);
    cudaGetSymbolAddress(&p_agg,  g_agg);
    cudaMemsetAsync(p_smax, 0, (size_t)N * NH * sizeof(unsigned), 0);
    cudaMemsetAsync(p_den,  0, (size_t)N * NH * sizeof(float), 0);
    cudaMemsetAsync(p_agg,  0, (size_t)N * H  * sizeof(float), 0);

    cudaFuncSetAttribute(k4_edge, cudaFuncAttributeMaxDynamicSharedMemorySize, SMEM4_BYTES);
    cudaFuncSetAttribute(k5_out,  cudaFuncAttributeMaxDynamicSharedMemorySize, SMEM5_BYTES);

    k1_proj<<<(N + 31) / 32, 256>>>(h, wq, wk, msg_w1, msg_b1, N);
    k2_scores<<<1184, 256>>>(wt, tfreq, tphase, eidx, dts, E);
    k3_softmax<<<(E + 255) / 256, 256>>>(eidx, E);
    k4_edge<<<296, 256, SMEM4_BYTES>>>(ef, msg_w1 + H * H, msg_w2, msg_b2, eidx, E);
    k5_out<<<(N + 31) / 32, 256, SMEM5_BYTES>>>(h, wo, nw1, nb1, nw2, nb2,
                                                nw3, nb3, t_ptr, tfreq, tphase, out, N);
}

// round 3
// speedup vs baseline: 1.0173x; 1.0173x over previous
#include <cuda_runtime.h>
#include <cstdint>

#define H   128
#define ED  32
#define NH  4
#define DH  32
#define TD  32
#define MH  256

#define MAXN 50048
#define MAXE 640064

// ---------------- scratch (module-level device memory; no allocs) ----------
__device__ __align__(128) float    g_hq  [(size_t)MAXN * H];
__device__ __align__(128) float    g_hk  [(size_t)MAXN * H];
__device__ __align__(128) float    g_hm1 [(size_t)MAXN * H];   // h @ W1a + b1
__device__ __align__(128) float    g_scores[(size_t)MAXE * NH];
__device__ __align__(128) float    g_ex    [(size_t)MAXE * NH];
__device__ __align__(128) unsigned g_smax  [(size_t)MAXN * NH];
__device__ __align__(128) float    g_den   [(size_t)MAXN * NH];
__device__ __align__(128) float    g_agg   [(size_t)MAXN * H];

// ---------------- helpers ---------------------------------------------------
__device__ __forceinline__ unsigned enc_f(float f) {
    unsigned u = __float_as_uint(f);
    return (u & 0x80000000u) ? ~u : (u | 0x80000000u);
}
__device__ __forceinline__ float dec_f(unsigned k) {
    unsigned u = (k & 0x80000000u) ? (k & 0x7FFFFFFFu) : ~k;
    return __uint_as_float(u);
}
__device__ __forceinline__ float silu_f(float x) {
    return x / (1.0f + __expf(-x));
}
__device__ __forceinline__ void red_add_v4(float* p, float4 v) {
    asm volatile("red.global.add.v4.f32 [%0], {%1,%2,%3,%4};"
                 :: "l"(p), "f"(v.x), "f"(v.y), "f"(v.z), "f"(v.w) : "memory");
}
__device__ __forceinline__ void fma4(float4& acc, float a, const float4& b) {
    acc.x = fmaf(a, b.x, acc.x);
    acc.y = fmaf(a, b.y, acc.y);
    acc.z = fmaf(a, b.z, acc.z);
    acc.w = fmaf(a, b.w, acc.w);
}

// ============================================================================
// K1: node projections  hq = h@wq, hk = h@wk, hm1 = h@W1a + b1
// 32 rows/block, 256 threads, weights streamed through smem in 32-k slabs.
// Activation reads vectorized (float4 across k).
// ============================================================================
__global__ void __launch_bounds__(256) k1_proj(
    const float* __restrict__ h,
    const float* __restrict__ wq, const float* __restrict__ wk,
    const float* __restrict__ mw1, const float* __restrict__ mb1, int N)
{
    __shared__ float sa[32 * H];
    __shared__ float sw[32 * H];
    const int tid  = threadIdx.x;
    const int row0 = blockIdx.x * 32;

    for (int i = tid; i < 32 * H / 4; i += 256) {
        int r = i >> 5, c4 = i & 31;
        float4 v = make_float4(0.f, 0.f, 0.f, 0.f);
        if (row0 + r < N) v = ((const float4*)(h + (size_t)(row0 + r) * H))[c4];
        ((float4*)sa)[i] = v;
    }
    __syncthreads();

    const int cg = tid & 31, rg = tid >> 5, c0 = cg << 2;

    #pragma unroll
    for (int m = 0; m < 3; m++) {
        const float* W = (m == 0) ? wq : (m == 1) ? wk : mw1;
        float4 acc[4];
        if (m == 2) {
            float4 b = ((const float4*)mb1)[cg];
            acc[0] = acc[1] = acc[2] = acc[3] = b;
        } else {
            acc[0] = acc[1] = acc[2] = acc[3] = make_float4(0.f, 0.f, 0.f, 0.f);
        }
        for (int ks = 0; ks < 4; ks++) {
            __syncthreads();
            for (int i = tid; i < 32 * H / 4; i += 256)
                ((float4*)sw)[i] = ((const float4*)(W + (size_t)ks * 32 * H))[i];
            __syncthreads();
            #pragma unroll
            for (int k4 = 0; k4 < 8; k4++) {
                float4 a0 = *(const float4*)&sa[(rg * 4 + 0) * H + ks * 32 + k4 * 4];
                float4 a1 = *(const float4*)&sa[(rg * 4 + 1) * H + ks * 32 + k4 * 4];
                float4 a2 = *(const float4*)&sa[(rg * 4 + 2) * H + ks * 32 + k4 * 4];
                float4 a3 = *(const float4*)&sa[(rg * 4 + 3) * H + ks * 32 + k4 * 4];
                float4 w4;
                w4 = *(const float4*)&sw[(k4 * 4 + 0) * H + c0];
                fma4(acc[0], a0.x, w4); fma4(acc[1], a1.x, w4);
                fma4(acc[2], a2.x, w4); fma4(acc[3], a3.x, w4);
                w4 = *(const float4*)&sw[(k4 * 4 + 1) * H + c0];
                fma4(acc[0], a0.y, w4); fma4(acc[1], a1.y, w4);
                fma4(acc[2], a2.y, w4); fma4(acc[3], a3.y, w4);
                w4 = *(const float4*)&sw[(k4 * 4 + 2) * H + c0];
                fma4(acc[0], a0.z, w4); fma4(acc[1], a1.z, w4);
                fma4(acc[2], a2.z, w4); fma4(acc[3], a3.z, w4);
                w4 = *(const float4*)&sw[(k4 * 4 + 3) * H + c0];
                fma4(acc[0], a0.w, w4); fma4(acc[1], a1.w, w4);
                fma4(acc[2], a2.w, w4); fma4(acc[3], a3.w, w4);
            }
        }
        float* O = (m == 0) ? g_hq : (m == 1) ? g_hk : g_hm1;
        #pragma unroll
        for (int i = 0; i < 4; i++) {
            int r = rg * 4 + i;
            if (row0 + r < N)
                *(float4*)&O[(size_t)(row0 + r) * H + c0] = acc[i];
        }
    }
}

// ============================================================================
// K2: per-edge attention scores + segment max.
// warp per edge: k_e = hk[src] + dt_feat@wt ; score = q.k / sqrt(DH)
// ============================================================================
__global__ void __launch_bounds__(256) k2_scores(
    const float* __restrict__ wt,
    const float* __restrict__ tfreq, const float* __restrict__ tphase,
    const int* __restrict__ eidx, const float* __restrict__ dts, int E)
{
    __shared__ float swt[TD * H];
    __shared__ float sfreq[TD], sphase[TD];
    __shared__ __align__(16) float sdtf[8][TD];
    const int tid = threadIdx.x;
    for (int i = tid; i < TD * H / 4; i += 256)
        ((float4*)swt)[i] = ((const float4*)wt)[i];
    if (tid < TD) { sfreq[tid] = tfreq[tid]; sphase[tid] = tphase[tid]; }
    __syncthreads();

    const int warp = tid >> 5, lane = tid & 31;
    const int c0 = lane << 2;
    for (int e = blockIdx.x * 8 + warp; e < E; e += gridDim.x * 8) {
        int tgt = eidx[e];
        int src = eidx[E + e];
        float dt = dts[e];
        sdtf[warp][lane] = cosf(dt * sfreq[lane] + sphase[lane]);
        __syncwarp();

        float4 kv = *(const float4*)&g_hk[(size_t)src * H + c0];
        #pragma unroll
        for (int d4 = 0; d4 < 8; d4++) {
            float4 f = *(const float4*)&sdtf[warp][d4 * 4];
            fma4(kv, f.x, *(const float4*)&swt[(d4 * 4 + 0) * H + c0]);
            fma4(kv, f.y, *(const float4*)&swt[(d4 * 4 + 1) * H + c0]);
            fma4(kv, f.z, *(const float4*)&swt[(d4 * 4 + 2) * H + c0]);
            fma4(kv, f.w, *(const float4*)&swt[(d4 * 4 + 3) * H + c0]);
        }
        float4 q4 = *(const float4*)&g_hq[(size_t)tgt * H + c0];
        float p = q4.x * kv.x + q4.y * kv.y + q4.z * kv.z + q4.w * kv.w;
        p += __shfl_xor_sync(0xffffffffu, p, 4);
        p += __shfl_xor_sync(0xffffffffu, p, 2);
        p += __shfl_xor_sync(0xffffffffu, p, 1);
        if ((lane & 7) == 0) {
            float s = p * 0.17677669529663687f;   // 1/sqrt(32)
            int hd = lane >> 3;
            g_scores[(size_t)e * NH + hd] = s;
            atomicMax(&g_smax[(size_t)tgt * NH + hd], enc_f(s));
        }
        __syncwarp();
    }
}

// ============================================================================
// K3: ex = exp(score - smax[tgt]); den[tgt] += ex   (one thread per edge)
// ============================================================================
__global__ void __launch_bounds__(256) k3_softmax(
    const int* __restrict__ eidx, int E)
{
    int e = blockIdx.x * 256 + threadIdx.x;
    if (e >= E) return;
    int tgt = eidx[e];
    float4 s4 = *(const float4*)&g_scores[(size_t)e * NH];
    uint4  m4 = *(const uint4*)&g_smax[(size_t)tgt * NH];
    float4 v;
    v.x = __expf(s4.x - dec_f(m4.x));
    v.y = __expf(s4.y - dec_f(m4.y));
    v.z = __expf(s4.z - dec_f(m4.z));
    v.w = __expf(s4.w - dec_f(m4.w));
    *(float4*)&g_ex[(size_t)e * NH] = v;
    red_add_v4(&g_den[(size_t)tgt * NH], v);
}

// ============================================================================
// K4: edge message MLP + attention-weighted scatter.
// hid = silu(hm1[src] + e@W1b)  (b1 folded into hm1)
// m   = hid @ msg_w2 + b2 ; agg[tgt] += attn * m   (red.global.add.v4)
// Persistent blocks; W1b + msg_w2 resident in shared.  32-edge tiles.
// Vectorized activation reads (float4 across k).
// ============================================================================
#define SMEM4_FLOATS (4096 + 16384 + 1024 + 4096 + 128 + 32)
#define SMEM4_BYTES  (SMEM4_FLOATS * 4)

__global__ void __launch_bounds__(256) k4_edge(
    const float* __restrict__ ef, const float* __restrict__ w1b,
    const float* __restrict__ w2, const float* __restrict__ b2,
    const int* __restrict__ eidx, int E)
{
    extern __shared__ float sm4[];
    float* sw1b = sm4;                 // [32][128]
    float* sw2  = sm4 + 4096;          // [128][128]
    float* sef  = sm4 + 20480;         // [32][32]
    float* shid = sm4 + 21504;         // [32][128]
    float* satt = sm4 + 25600;         // [32][4]
    int*   stgt = (int*)(sm4 + 25728); // [32]

    const int tid = threadIdx.x;
    for (int i = tid; i < 4096 / 4; i += 256)
        ((float4*)sw1b)[i] = ((const float4*)w1b)[i];
    for (int i = tid; i < 16384 / 4; i += 256)
        ((float4*)sw2)[i] = ((const float4*)w2)[i];

    const int cg = tid & 31, rg = tid >> 5, c0 = cg << 2, hd = cg >> 3;
    const float4 b2v = ((const float4*)b2)[cg];
    const int ntiles = (E + 31) >> 5;

    for (int tile = blockIdx.x; tile < ntiles; tile += gridDim.x) {
        const int e0 = tile << 5;
        __syncthreads();   // protects smem from previous tile (and weight loads, tile 0)

        if (tid < 128) {
            int r = tid >> 2, hh = tid & 3;
            int e = e0 + r;
            float a = 0.f; int tg = 0;
            if (e < E) {
                tg = eidx[e];
                a  = g_ex[(size_t)e * NH + hh] / g_den[(size_t)tg * NH + hh];
            }
            satt[r * 4 + hh] = a;
            if (hh == 0) stgt[r] = tg;
        }
        for (int i = tid; i < 1024 / 4; i += 256) {
            int r = i >> 3, c4 = i & 7;
            int e = e0 + r;
            float4 v = make_float4(0.f, 0.f, 0.f, 0.f);
            if (e < E) v = ((const float4*)(ef + (size_t)e * ED))[c4];
            ((float4*)sef)[i] = v;
        }
        __syncthreads();

        // phase A: pre-activation = hm1[src] + ef @ W1b, then silu -> shid
        float4 acc[4];
        #pragma unroll
        for (int i = 0; i < 4; i++) {
            int e = e0 + rg * 4 + i;
            int src = (e < E) ? eidx[E + e] : 0;
            acc[i] = *(const float4*)&g_hm1[(size_t)src * H + c0];
        }
        #pragma unroll
        for (int d4 = 0; d4 < 8; d4++) {
            float4 a0 = *(const float4*)&sef[(rg * 4 + 0) * ED + d4 * 4];
            float4 a1 = *(const float4*)&sef[(rg * 4 + 1) * ED + d4 * 4];
            float4 a2 = *(const float4*)&sef[(rg * 4 + 2) * ED + d4 * 4];
            float4 a3 = *(const float4*)&sef[(rg * 4 + 3) * ED + d4 * 4];
            float4 w4;
            w4 = *(const float4*)&sw1b[(d4 * 4 + 0) * H + c0];
            fma4(acc[0], a0.x, w4); fma4(acc[1], a1.x, w4);
            fma4(acc[2], a2.x, w4); fma4(acc[3], a3.x, w4);
            w4 = *(const float4*)&sw1b[(d4 * 4 + 1) * H + c0];
            fma4(acc[0], a0.y, w4); fma4(acc[1], a1.y, w4);
            fma4(acc[2], a2.y, w4); fma4(acc[3], a3.y, w4);
            w4 = *(const float4*)&sw1b[(d4 * 4 + 2) * H + c0];
            fma4(acc[0], a0.z, w4); fma4(acc[1], a1.z, w4);
            fma4(acc[2], a2.z, w4); fma4(acc[3], a3.z, w4);
            w4 = *(const float4*)&sw1b[(d4 * 4 + 3) * H + c0];
            fma4(acc[0], a0.w, w4); fma4(acc[1], a1.w, w4);
            fma4(acc[2], a2.w, w4); fma4(acc[3], a3.w, w4);
        }
        #pragma unroll
        for (int i = 0; i < 4; i++) {
            float4 s;
            s.x = silu_f(acc[i].x); s.y = silu_f(acc[i].y);
            s.z = silu_f(acc[i].z); s.w = silu_f(acc[i].w);
            *(float4*)&shid[(rg * 4 + i) * H + c0] = s;
        }
        __syncthreads();

        // phase B: m = hid @ msg_w2 + b2   (vectorized a-reads)
        float4 m4[4];
        #pragma unroll
        for (int i = 0; i < 4; i++) m4[i] = b2v;
        #pragma unroll
        for (int k4 = 0; k4 < 32; k4++) {
            float4 a0 = *(const float4*)&shid[(rg * 4 + 0) * H + k4 * 4];
            float4 a1 = *(const float4*)&shid[(rg * 4 + 1) * H + k4 * 4];
            float4 a2 = *(const float4*)&shid[(rg * 4 + 2) * H + k4 * 4];
            float4 a3 = *(const float4*)&shid[(rg * 4 + 3) * H + k4 * 4];
            float4 w4;
            w4 = *(const float4*)&sw2[(k4 * 4 + 0) * H + c0];
            fma4(m4[0], a0.x, w4); fma4(m4[1], a1.x, w4);
            fma4(m4[2], a2.x, w4); fma4(m4[3], a3.x, w4);
            w4 = *(const float4*)&sw2[(k4 * 4 + 1) * H + c0];
            fma4(m4[0], a0.y, w4); fma4(m4[1], a1.y, w4);
            fma4(m4[2], a2.y, w4); fma4(m4[3], a3.y, w4);
            w4 = *(const float4*)&sw2[(k4 * 4 + 2) * H + c0];
            fma4(m4[0], a0.z, w4); fma4(m4[1], a1.z, w4);
            fma4(m4[2], a2.z, w4); fma4(m4[3], a3.z, w4);
            w4 = *(const float4*)&sw2[(k4 * 4 + 3) * H + c0];
            fma4(m4[0], a0.w, w4); fma4(m4[1], a1.w, w4);
            fma4(m4[2], a2.w, w4); fma4(m4[3], a3.w, w4);
        }
        // phase C: scatter attn * m
        #pragma unroll
        for (int i = 0; i < 4; i++) {
            int r = rg * 4 + i, e = e0 + r;
            if (e < E) {
                float a  = satt[r * 4 + hd];
                int   tg = stgt[r];
                float4 v = make_float4(a * m4[i].x, a * m4[i].y,
                                       a * m4[i].z, a * m4[i].w);
                red_add_v4(&g_agg[(size_t)tg * H + c0], v);
            }
        }
    }
}

// ============================================================================
// K5: per-node output:  aggregated = agg@wo ; x=[h||aggregated||t_feat] ;
//     dh = (silu(silu(x@w1+b1)@w2+b2))@w3 + b3
// 32 nodes/block; vectorized activation reads.
// ============================================================================
#define SMEM5_FLOATS (9216 + 8192 + 8192)
#define SMEM5_BYTES  (SMEM5_FLOATS * 4)

__global__ void __launch_bounds__(256) k5_out(
    const float* __restrict__ h,  const float* __restrict__ wo,
    const float* __restrict__ w1, const float* __restrict__ b1,
    const float* __restrict__ w2, const float* __restrict__ b2,
    const float* __restrict__ w3, const float* __restrict__ b3,
    const float* __restrict__ tptr,
    const float* __restrict__ tfreq, const float* __restrict__ tphase,
    float* __restrict__ out, int N)
{
    extern __shared__ float sm5[];
    float* sx = sm5;                 // [32][288]
    float* sy = sm5 + 9216;          // [32][256]
    float* sw = sm5 + 9216 + 8192;   // up to [32][256]

    const int tid  = threadIdx.x;
    const int row0 = blockIdx.x * 32;
    const float t  = tptr[0];

    // t_feat (same vector for all rows)
    for (int i = tid; i < 32 * TD; i += 256) {
        int r = i >> 5, j = i & 31;
        sx[r * 288 + 256 + j] = cosf(t * tfreq[j] + tphase[j]);
    }
    // h block -> sx[:, 0:128]
    for (int i = tid; i < 32 * H / 4; i += 256) {
        int r = i >> 5, c4 = i & 31;
        float4 v = make_float4(0.f, 0.f, 0.f, 0.f);
        if (row0 + r < N) v = ((const float4*)(h + (size_t)(row0 + r) * H))[c4];
        *(float4*)&sx[r * 288 + c4 * 4] = v;
    }
    // agg block -> sy (temporary A-tile)
    for (int i = tid; i < 32 * H / 4; i += 256) {
        int r = i >> 5, c4 = i & 31;
        float4 v = make_float4(0.f, 0.f, 0.f, 0.f);
        if (row0 + r < N) v = ((const float4*)(g_agg + (size_t)(row0 + r) * H))[c4];
        ((float4*)sy)[i] = v;
    }
    __syncthreads();

    const int cg = tid & 31, rg = tid >> 5, c0 = cg << 2;

    // stage 0: aggregated = aggtile @ wo  -> sx[:, 128:256]
    {
        float4 acc[4];
        #pragma unroll
        for (int i = 0; i < 4; i++) acc[i] = make_float4(0.f, 0.f, 0.f, 0.f);
        for (int ks = 0; ks < 4; ks++) {
            __syncthreads();
            for (int i = tid; i < 32 * H / 4; i += 256)
                ((float4*)sw)[i] = ((const float4*)(wo + (size_t)ks * 32 * H))[i];
            __syncthreads();
            #pragma unroll
            for (int k4 = 0; k4 < 8; k4++) {
                float4 a0 = *(const float4*)&sy[(rg * 4 + 0) * H + ks * 32 + k4 * 4];
                float4 a1 = *(const float4*)&sy[(rg * 4 + 1) * H + ks * 32 + k4 * 4];
                float4 a2 = *(const float4*)&sy[(rg * 4 + 2) * H + ks * 32 + k4 * 4];
                float4 a3 = *(const float4*)&sy[(rg * 4 + 3) * H + ks * 32 + k4 * 4];
                float4 w4;
                w4 = *(const float4*)&sw[(k4 * 4 + 0) * H + c0];
                fma4(acc[0], a0.x, w4); fma4(acc[1], a1.x, w4);
                fma4(acc[2], a2.x, w4); fma4(acc[3], a3.x, w4);
                w4 = *(const float4*)&sw[(k4 * 4 + 1) * H + c0];
                fma4(acc[0], a0.y, w4); fma4(acc[1], a1.y, w4);
                fma4(acc[2], a2.y, w4); fma4(acc[3], a3.y, w4);
                w4 = *(const float4*)&sw[(k4 * 4 + 2) * H + c0];
                fma4(acc[0], a0.z, w4); fma4(acc[1], a1.z, w4);
                fma4(acc[2], a2.z, w4); fma4(acc[3], a3.z, w4);
                w4 = *(const float4*)&sw[(k4 * 4 + 3) * H + c0];
                fma4(acc[0], a0.w, w4); fma4(acc[1], a1.w, w4);
                fma4(acc[2], a2.w, w4); fma4(acc[3], a3.w, w4);
            }
        }
        __syncthreads();
        #pragma unroll
        for (int i = 0; i < 4; i++)
            *(float4*)&sx[(rg * 4 + i) * 288 + 128 + c0] = acc[i];
    }
    __syncthreads();

    const int cgB = tid & 63, rgB = tid >> 6, cB0 = cgB << 2;

    // stage 1: y1 = silu(x @ w1 + b1) -> sy [32][256]
    {
        float4 acc[8];
        float4 bb = ((const float4*)b1)[cgB];
        #pragma unroll
        for (int i = 0; i < 8; i++) acc[i] = bb;
        for (int ks = 0; ks < 9; ks++) {
            __syncthreads();
            for (int i = tid; i < 32 * MH / 4; i += 256)
                ((float4*)sw)[i] = ((const float4*)(w1 + (size_t)ks * 32 * MH))[i];
            __syncthreads();
            #pragma unroll
            for (int k4 = 0; k4 < 8; k4++) {
                float4 av[8];
                #pragma unroll
                for (int i = 0; i < 8; i++)
                    av[i] = *(const float4*)&sx[(rgB * 8 + i) * 288 + ks * 32 + k4 * 4];
                float4 w4;
                w4 = *(const float4*)&sw[(k4 * 4 + 0) * MH + cB0];
                #pragma unroll
                for (int i = 0; i < 8; i++) fma4(acc[i], av[i].x, w4);
                w4 = *(const float4*)&sw[(k4 * 4 + 1) * MH + cB0];
                #pragma unroll
                for (int i = 0; i < 8; i++) fma4(acc[i], av[i].y, w4);
                w4 = *(const float4*)&sw[(k4 * 4 + 2) * MH + cB0];
                #pragma unroll
                for (int i = 0; i < 8; i++) fma4(acc[i], av[i].z, w4);
                w4 = *(const float4*)&sw[(k4 * 4 + 3) * MH + cB0];
                #pragma unroll
                for (int i = 0; i < 8; i++) fma4(acc[i], av[i].w, w4);
            }
        }
        __syncthreads();
        #pragma unroll
        for (int i = 0; i < 8; i++) {
            float4 s;
            s.x = silu_f(acc[i].x); s.y = silu_f(acc[i].y);
            s.z = silu_f(acc[i].z); s.w = silu_f(acc[i].w);
            *(float4*)&sy[(rgB * 8 + i) * MH + cB0] = s;
        }
    }
    __syncthreads();

    // stage 2: y2 = silu(y1 @ w2 + b2) -> sx rows (stride 288), cols 0:256
    {
        float4 acc[8];
        float4 bb = ((const float4*)b2)[cgB];
        #pragma unroll
        for (int i = 0; i < 8; i++) acc[i] = bb;
        for (int ks = 0; ks < 8; ks++) {
            __syncthreads();
            for (int i = tid; i < 32 * MH / 4; i += 256)
                ((float4*)sw)[i] = ((const float4*)(w2 + (size_t)ks * 32 * MH))[i];
            __syncthreads();
            #pragma unroll
            for (int k4 = 0; k4 < 8; k4++) {
                float4 av[8];
                #pragma unroll
                for (int i = 0; i < 8; i++)
                    av[i] = *(const float4*)&sy[(rgB * 8 + i) * MH + ks * 32 + k4 * 4];
                float4 w4;
                w4 = *(const float4*)&sw[(k4 * 4 + 0) * MH + cB0];
                #pragma unroll
                for (int i = 0; i < 8; i++) fma4(acc[i], av[i].x, w4);
                w4 = *(const float4*)&sw[(k4 * 4 + 1) * MH + cB0];
                #pragma unroll
                for (int i = 0; i < 8; i++) fma4(acc[i], av[i].y, w4);
                w4 = *(const float4*)&sw[(k4 * 4 + 2) * MH + cB0];
                #pragma unroll
                for (int i = 0; i < 8; i++) fma4(acc[i], av[i].z, w4);
                w4 = *(const float4*)&sw[(k4 * 4 + 3) * MH + cB0];
                #pragma unroll
                for (int i = 0; i < 8; i++) fma4(acc[i], av[i].w, w4);
            }
        }
        __syncthreads();
        #pragma unroll
        for (int i = 0; i < 8; i++) {
            float4 s;
            s.x = silu_f(acc[i].x); s.y = silu_f(acc[i].y);
            s.z = silu_f(acc[i].z); s.w = silu_f(acc[i].w);
            *(float4*)&sx[(rgB * 8 + i) * 288 + cB0] = s;
        }
    }
    __syncthreads();

    // stage 3: out = y2 @ w3 + b3
    {
        float4 acc[4];
        float4 bb = ((const float4*)b3)[cg];
        #pragma unroll
        for (int i = 0; i < 4; i++) acc[i] = bb;
        for (int ks = 0; ks < 8; ks++) {
            __syncthreads();
            for (int i = tid; i < 32 * H / 4; i += 256)
                ((float4*)sw)[i] = ((const float4*)(w3 + (size_t)ks * 32 * H))[i];
            __syncthreads();
            #pragma unroll
            for (int k4 = 0; k4 < 8; k4++) {
                float4 a0 = *(const float4*)&sx[(rg * 4 + 0) * 288 + ks * 32 + k4 * 4];
                float4 a1 = *(const float4*)&sx[(rg * 4 + 1) * 288 + ks * 32 + k4 * 4];
                float4 a2 = *(const float4*)&sx[(rg * 4 + 2) * 288 + ks * 32 + k4 * 4];
                float4 a3 = *(const float4*)&sx[(rg * 4 + 3) * 288 + ks * 32 + k4 * 4];
                float4 w4;
                w4 = *(const float4*)&sw[(k4 * 4 + 0) * H + c0];
                fma4(acc[0], a0.x, w4); fma4(acc[1], a1.x, w4);
                fma4(acc[2], a2.x, w4); fma4(acc[3], a3.x, w4);
                w4 = *(const float4*)&sw[(k4 * 4 + 1) * H + c0];
                fma4(acc[0], a0.y, w4); fma4(acc[1], a1.y, w4);
                fma4(acc[2], a2.y, w4); fma4(acc[3], a3.y, w4);
                w4 = *(const float4*)&sw[(k4 * 4 + 2) * H + c0];
                fma4(acc[0], a0.z, w4); fma4(acc[1], a1.z, w4);
                fma4(acc[2], a2.z, w4); fma4(acc[3], a3.z, w4);
                w4 = *(const float4*)&sw[(k4 * 4 + 3) * H + c0];
                fma4(acc[0], a0.w, w4); fma4(acc[1], a1.w, w4);
                fma4(acc[2], a2.w, w4); fma4(acc[3], a3.w, w4);
            }
        }
        #pragma unroll
        for (int i = 0; i < 4; i++) {
            int r = rg * 4 + i;
            if (row0 + r < N)
                *(float4*)&out[(size_t)(row0 + r) * H + c0] = acc[i];
        }
    }
}

// ============================================================================
extern "C" void kernel_launch(void* const* d_in, const int* in_sizes, int n_in,
                              void* d_out, int out_size)
{
    // num_nodes (python int) may or may not appear as input #5; detect by size.
    int wbase = (in_sizes[5] == (H + ED) * H) ? 5 : 6;

    const float* t_ptr  = (const float*)d_in[0];
    const float* h      = (const float*)d_in[1];
    const int*   eidx   = (const int*)  d_in[2];
    const float* ef     = (const float*)d_in[3];
    const float* dts    = (const float*)d_in[4];
    const float* msg_w1 = (const float*)d_in[wbase + 0];
    const float* msg_b1 = (const float*)d_in[wbase + 1];
    const float* msg_w2 = (const float*)d_in[wbase + 2];
    const float* msg_b2 = (const float*)d_in[wbase + 3];
    const float* wq     = (const float*)d_in[wbase + 4];
    const float* wk     = (const float*)d_in[wbase + 5];
    const float* wt     = (const float*)d_in[wbase + 6];
    const float* wo     = (const float*)d_in[wbase + 7];
    const float* tfreq  = (const float*)d_in[wbase + 8];
    const float* tphase = (const float*)d_in[wbase + 9];
    const float* nw1    = (const float*)d_in[wbase + 10];
    const float* nb1    = (const float*)d_in[wbase + 11];
    const float* nw2    = (const float*)d_in[wbase + 12];
    const float* nb2    = (const float*)d_in[wbase + 13];
    const float* nw3    = (const float*)d_in[wbase + 14];
    const float* nb3    = (const float*)d_in[wbase + 15];
    float* out = (float*)d_out;

    const int N = in_sizes[1] / H;
    const int E = in_sizes[4];

    void *p_smax, *p_den, *p_agg;
    cudaGetSymbolAddress(&p_smax, g_smax);
    cudaGetSymbolAddress(&p_den,  g_den);
    cudaGetSymbolAddress(&p_agg,  g_agg);
    cudaMemsetAsync(p_smax, 0, (size_t)N * NH * sizeof(unsigned), 0);
    cudaMemsetAsync(p_den,  0, (size_t)N * NH * sizeof(float), 0);
    cudaMemsetAsync(p_agg,  0, (size_t)N * H  * sizeof(float), 0);

    cudaFuncSetAttribute(k4_edge, cudaFuncAttributeMaxDynamicSharedMemorySize, SMEM4_BYTES);
    cudaFuncSetAttribute(k5_out,  cudaFuncAttributeMaxDynamicSharedMemorySize, SMEM5_BYTES);

    k1_proj<<<(N + 31) / 32, 256>>>(h, wq, wk, msg_w1, msg_b1, N);
    k2_scores<<<1184, 256>>>(wt, tfreq, tphase, eidx, dts, E);
    k3_softmax<<<(E + 255) / 256, 256>>>(eidx, E);
    k4_edge<<<296, 256, SMEM4_BYTES>>>(ef, msg_w1 + H * H, msg_w2, msg_b2, eidx, E);
    k5_out<<<(N + 31) / 32, 256, SMEM5_BYTES>>>(h, wo, nw1, nb1, nw2, nb2,
                                                nw3, nb3, t_ptr, tfreq, tphase, out, N);
}